// round 4
// baseline (speedup 1.0000x reference)
#include <cuda_runtime.h>
#include <math.h>

#define NY 1024
#define NX 1024
#define NSTEPS 64
#define NPTS (NY*NX)

__device__ float g_H0[NPTS];
__device__ float g_H1[NPTS];
__device__ float g_smb[NPTS];
__device__ int g_maxDbits[NSTEPS];
__device__ unsigned g_arrive;
__device__ unsigned g_done[256 * 8];     // per-block step flags, padded

// fence-free gpu-scope sync primitives (no CCTL.IVALL L1 flush)
static __device__ __forceinline__ unsigned ld_acq(const unsigned* p) {
    unsigned v;
    asm volatile("ld.acquire.gpu.global.u32 %0, [%1];" : "=r"(v) : "l"(p) : "memory");
    return v;
}
static __device__ __forceinline__ void red_add_rel(unsigned* p, unsigned v) {
    asm volatile("red.release.gpu.global.add.u32 [%0], %1;" :: "l"(p), "r"(v) : "memory");
}

static __device__ __forceinline__ float smb_of(float Zs, float precip, float mask,
                                               float tma_low, float tmj_low) {
    float T_ma = tma_low - 0.0065f * Zs;
    float T_mj = tmj_low - 0.0065f * Zs;
    float acc = precip * (T_ma < 0.0f ? 1.0f : 0.0f);
    float abl = 0.5f * fmaxf(T_mj, 0.0f);
    return (acc - abl) * mask;
}

__global__ void k_reset() {
    int t = threadIdx.x;
    if (t == 0) g_arrive = 0u;
    if (t < NSTEPS) g_maxDbits[t] = 0;
    for (int k = t; k < 256 * 8; k += blockDim.x) g_done[k] = 0u;
}

#define INV 0.02f

__global__ void __launch_bounds__(1024, 1)
k_persist(const float* __restrict__ precip,
          const float* __restrict__ tma_p,
          const float* __restrict__ tmj_p,
          const float* __restrict__ Ztopo,
          const float* __restrict__ mask,
          float* __restrict__ out) {
    __shared__ float sD[8][NX];          // D rows r0-1 .. r1-1 (slot = row-(r0-1))
    __shared__ float wred[32];

    const int i   = threadIdx.x;         // column
    const int nb  = gridDim.x;
    const int bid = blockIdx.x;
    const int lane = i & 31, wid = i >> 5;
    const unsigned FULL = 0xFFFFFFFFu;

    int base = NY / nb, rem = NY % nb;
    int r0 = bid * base + (bid < rem ? bid : rem);
    int r1 = r0 + base + (bid < rem ? 1 : 0);

    const float tma = tma_p[0], tmj = tmj_p[0];
    const float CFACT = (float)(1e-17 * 8927.1 * 8927.1 * 8927.1);  // FD*(rho*g)^3
    const bool iIn = (i > 0) && (i < NX - 1);

    // ---- init: H=0, smb(Ztopo); D(0) = EPS uniformly ----
    for (int j = r0; j < r1; j++) {
        int idx = j * NX + i;
        g_H0[idx] = 0.0f;
        g_smb[idx] = smb_of(Ztopo[idx], precip[idx], mask[idx], tma, tmj);
    }
    #pragma unroll
    for (int k = 0; k < 8; k++) sD[k][i] = 1e-10f;

    unsigned target = nb;
    // global barrier (init)
    __syncthreads();
    if (i == 0) { red_add_rel(&g_arrive, 1u); while (ld_acq(&g_arrive) < target) __nanosleep(20); }
    __syncthreads();
    target += nb;

    float time = 0.0f, tlast = 0.0f;

    for (int s = 0; s < NSTEPS; s++) {
        const float* Hr = (s & 1) ? g_H1 : g_H0;
        float*       Hw = (s & 1) ? g_H0 : g_H1;

        // ---- dt for this step ----
        float maxD = (s == 0) ? 1e-10f : __int_as_float(__ldcg(&g_maxDbits[s]));
        float dt = fminf(2500.0f / (2.7f * maxD), 0.5f);
        if (!(time < 32.0f)) dt = 0.0f;
        float tnew = time + dt;
        bool  upd  = (tnew - tlast) >= 5.0f;
        const bool last = (s == NSTEPS - 1);

        // ---- fused H-update sweep over own rows r0..r1-1 ----
        // rolling state: row j-1 center z (zU); row j: zL,zC,zR,hC,ZtC; D pair of row j-1
        float zU = 0.f, zC, zL, zR, hC, ZtC;
        {
            if (r0 > 0) {
                float h = __ldcg(&Hr[(r0 - 1) * NX + i]);
                zU = Ztopo[(r0 - 1) * NX + i] + h;
            }
            hC  = Hr[r0 * NX + i];
            ZtC = Ztopo[r0 * NX + i];
            zC  = ZtC + hC;
            zL = __shfl_up_sync(FULL, zC, 1);
            if (lane == 0)  zL = (i > 0)      ? (Ztopo[r0 * NX + i - 1] + Hr[r0 * NX + i - 1]) : 0.f;
            zR = __shfl_down_sync(FULL, zC, 1);
            if (lane == 31) zR = (i < NX - 1) ? (Ztopo[r0 * NX + i + 1] + Hr[r0 * NX + i + 1]) : 0.f;
        }
        float Dmm = (i > 0) ? sD[0][i - 1] : 0.f;
        float Dm0 = sD[0][i];

        for (int j = r0; j < r1; j++) {
            int idx = j * NX + i;
            // prefetch row j+1
            float hD = 0.f, ZtD = 0.f, zD = 0.f;
            if (j + 1 < NY) {
                hD  = (j + 1 == r1) ? __ldcg(&Hr[idx + NX]) : Hr[idx + NX];
                ZtD = Ztopo[idx + NX];
                zD  = ZtD + hD;
            }
            int lr = j - r0 + 1;                  // D slot for row j
            float D00 = sD[lr][i];
            float D0m = (i > 0) ? sD[lr][i - 1] : 0.f;

            float Hn;
            if (iIn && (j > 0) && (j < NY - 1)) {
                float qxr = -(0.5f * (Dm0 + D00)) * (zR - zC) * INV;
                float qxl = -(0.5f * (Dmm + D0m)) * (zC - zL) * INV;
                float qyd = -(0.5f * (D0m + D00)) * (zD - zC) * INV;
                float qyu = -(0.5f * (Dmm + Dm0)) * (zC - zU) * INV;
                float dHdt = -((qxr - qxl) * INV + (qyd - qyu) * INV);
                Hn = hC + dt * (dHdt + g_smb[idx]);
            } else {
                Hn = hC;
            }
            Hn = fmaxf(Hn, 0.0f);
            Hw[idx] = Hn;
            if (upd) {
                float Zn = ZtC + Hn;
                g_smb[idx] = smb_of(Zn, precip[idx], mask[idx], tma, tmj);
            }
            if (last) out[idx] = Hn;
            // roll
            zU = zC; hC = hD; ZtC = ZtD; zC = zD;
            zL = __shfl_up_sync(FULL, zD, 1);
            if (lane == 0)
                zL = (i > 0 && j + 1 < NY)
                   ? (Ztopo[idx + NX - 1] + ((j + 1 == r1) ? __ldcg(&Hr[idx + NX - 1]) : Hr[idx + NX - 1])) : 0.f;
            zR = __shfl_down_sync(FULL, zD, 1);
            if (lane == 31)
                zR = (i < NX - 1 && j + 1 < NY)
                   ? (Ztopo[idx + NX + 1] + ((j + 1 == r1) ? __ldcg(&Hr[idx + NX + 1]) : Hr[idx + NX + 1])) : 0.f;
            Dmm = D0m; Dm0 = D00;
        }

        if (last) break;   // no next-step D/max needed

        __syncthreads();                          // Hw band + sD reads complete
        if (i == 0) red_add_rel(&g_done[bid * 8], 1u);   // publish Hn band

        // ---- interior D(s+1): rows r0..r1-2 (uses own Hw, L1-hot) ----
        float lmax = 0.0f;
        {
            float hA = Hw[r0 * NX + i], ZtA = Ztopo[r0 * NX + i];
            float hAr = __shfl_down_sync(FULL, hA, 1);
            float ZtAr = __shfl_down_sync(FULL, ZtA, 1);
            if (lane == 31 && i < NX - 1) { hAr = Hw[r0 * NX + i + 1]; ZtAr = Ztopo[r0 * NX + i + 1]; }
            for (int j = r0; j < r1 - 1; j++) {
                int idx = (j + 1) * NX + i;
                float hB = Hw[idx], ZtB = Ztopo[idx];
                float hBr = __shfl_down_sync(FULL, hB, 1);
                float ZtBr = __shfl_down_sync(FULL, ZtB, 1);
                if (lane == 31 && i < NX - 1) { hBr = Hw[idx + 1]; ZtBr = Ztopo[idx + 1]; }
                if (i < NX - 1) {
                    float z00 = ZtA + hA,  z01 = ZtAr + hAr;
                    float z10 = ZtB + hB,  z11 = ZtBr + hBr;
                    float H_avg = 0.25f * (((hA + hBr) + hAr) + hB);
                    float sx = 0.5f * ((z01 - z00) * INV + (z11 - z10) * INV);
                    float sy = 0.5f * ((z10 - z00) * INV + (z11 - z01) * INV);
                    float s2 = sx * sx + sy * sy + 1e-10f;
                    float h2 = H_avg * H_avg;
                    float D = CFACT * (h2 * h2 * H_avg) * s2 + 1e-10f;
                    sD[j - r0 + 1][i] = D;
                    lmax = fmaxf(lmax, D);
                }
                hA = hB; ZtA = ZtB; hAr = hBr; ZtAr = ZtBr;
            }
        }

        // ---- wait neighbors' Hn bands, then boundary D rows ----
        if (i == 0 && bid > 0)       { while (ld_acq(&g_done[(bid - 1) * 8]) < (unsigned)(s + 1)) __nanosleep(20); }
        if (i == 32 && bid < nb - 1) { while (ld_acq(&g_done[(bid + 1) * 8]) < (unsigned)(s + 1)) __nanosleep(20); }
        __syncthreads();

        if (r0 >= 1 && i < NX - 1) {              // D row r0-1
            int ia = (r0 - 1) * NX + i, ib = r0 * NX + i;
            float hA = __ldcg(&Hw[ia]), hAr = __ldcg(&Hw[ia + 1]);
            float hB = Hw[ib],          hBr = Hw[ib + 1];
            float z00 = Ztopo[ia] + hA, z01 = Ztopo[ia + 1] + hAr;
            float z10 = Ztopo[ib] + hB, z11 = Ztopo[ib + 1] + hBr;
            float H_avg = 0.25f * (((hA + hBr) + hAr) + hB);
            float sx = 0.5f * ((z01 - z00) * INV + (z11 - z10) * INV);
            float sy = 0.5f * ((z10 - z00) * INV + (z11 - z01) * INV);
            float s2 = sx * sx + sy * sy + 1e-10f;
            float h2 = H_avg * H_avg;
            float D = CFACT * (h2 * h2 * H_avg) * s2 + 1e-10f;
            sD[0][i] = D;
            lmax = fmaxf(lmax, D);
        }
        if (r1 <= NY - 1 && i < NX - 1) {         // D row r1-1
            int ia = (r1 - 1) * NX + i, ib = r1 * NX + i;
            float hA = Hw[ia],          hAr = Hw[ia + 1];
            float hB = __ldcg(&Hw[ib]), hBr = __ldcg(&Hw[ib + 1]);
            float z00 = Ztopo[ia] + hA, z01 = Ztopo[ia + 1] + hAr;
            float z10 = Ztopo[ib] + hB, z11 = Ztopo[ib + 1] + hBr;
            float H_avg = 0.25f * (((hA + hBr) + hAr) + hB);
            float sx = 0.5f * ((z01 - z00) * INV + (z11 - z10) * INV);
            float sy = 0.5f * ((z10 - z00) * INV + (z11 - z01) * INV);
            float s2 = sx * sx + sy * sy + 1e-10f;
            float h2 = H_avg * H_avg;
            float D = CFACT * (h2 * h2 * H_avg) * s2 + 1e-10f;
            sD[r1 - r0][i] = D;
            lmax = fmaxf(lmax, D);
        }

        // ---- block max -> atomicMax slot s+1, then ONE global barrier ----
        #pragma unroll
        for (int o = 16; o > 0; o >>= 1)
            lmax = fmaxf(lmax, __shfl_xor_sync(FULL, lmax, o));
        if (lane == 0) wred[wid] = lmax;
        __syncthreads();
        if (wid == 0) {
            float m = wred[lane];
            #pragma unroll
            for (int o = 16; o > 0; o >>= 1)
                m = fmaxf(m, __shfl_xor_sync(FULL, m, o));
            if (lane == 0) atomicMax(&g_maxDbits[s + 1], __float_as_int(m));
        }
        __syncthreads();
        if (i == 0) { red_add_rel(&g_arrive, 1u); while (ld_acq(&g_arrive) < target) __nanosleep(20); }
        __syncthreads();
        target += nb;

        time = tnew;
        if (upd) tlast = tnew;
    }
}

extern "C" void kernel_launch(void* const* d_in, const int* in_sizes, int n_in,
                              void* d_out, int out_size) {
    const float* precip = (const float*)d_in[0];
    const float* tma_p  = (const float*)d_in[1];
    const float* tmj_p  = (const float*)d_in[2];
    const float* Ztopo  = (const float*)d_in[3];
    const float* mask   = (const float*)d_in[4];
    float* out = (float*)d_out;

    int dev = 0;
    cudaGetDevice(&dev);
    int sms = 0;
    cudaDeviceGetAttribute(&sms, cudaDevAttrMultiProcessorCount, dev);
    if (sms < 1) sms = 1;
    if (sms > 256) sms = 256;

    k_reset<<<1, 1024>>>();
    k_persist<<<sms, 1024>>>(precip, tma_p, tmj_p, Ztopo, mask, out);
}

// round 5
// speedup vs baseline: 1.5353x; 1.5353x over previous
#include <cuda_runtime.h>
#include <math.h>

#define NY 1024
#define NX 1024
#define NXP 1026
#define NSTEPS 64
#define NPTS (NY*NX)
#define INV 0.02f

__device__ float g_H0[NPTS];
__device__ float g_H1[NPTS];
__device__ float g_smb[NPTS];
__device__ int g_maxDbits[NSTEPS];
__device__ unsigned g_arrive;
__device__ unsigned g_done[256 * 8];

static __device__ __forceinline__ unsigned ld_acq(const unsigned* p) {
    unsigned v;
    asm volatile("ld.acquire.gpu.global.u32 %0, [%1];" : "=r"(v) : "l"(p) : "memory");
    return v;
}
static __device__ __forceinline__ void red_add_rel(unsigned* p, unsigned v) {
    asm volatile("red.release.gpu.global.add.u32 [%0], %1;" :: "l"(p), "r"(v) : "memory");
}

static __device__ __forceinline__ float smb_of(float Zs, float precip, float mask,
                                               float tma_low, float tmj_low) {
    float T_ma = tma_low - 0.0065f * Zs;
    float T_mj = tmj_low - 0.0065f * Zs;
    float acc = precip * (T_ma < 0.0f ? 1.0f : 0.0f);
    float abl = 0.5f * fmaxf(T_mj, 0.0f);
    return (acc - abl) * mask;
}

__global__ void k_reset() {
    int t = threadIdx.x;
    if (t == 0) g_arrive = 0u;
    if (t < NSTEPS) g_maxDbits[t] = 0;
    for (int k = t; k < 256 * 8; k += blockDim.x) g_done[k] = 0u;
}

__global__ void __launch_bounds__(1024, 1)
k_persist(const float* __restrict__ precip,
          const float* __restrict__ tma_p,
          const float* __restrict__ tmj_p,
          const float* __restrict__ Ztopo,
          const float* __restrict__ mask,
          float* __restrict__ out) {
    extern __shared__ float sm[];
    float* sZ  = sm;                    // 3 * NXP  (z of read state, rows ring, padded)
    float* sHw = sZ  + 3 * NXP;         // 3 * NXP  (Hn rows ring, padded)
    float* sZn = sHw + 3 * NXP;         // 3 * NXP  (Zn rows ring, padded)
    float* sDb = sZn + 3 * NXP;         // 8 * NX   (persistent D band: slot = row-(r0-1))
    __shared__ float wred[32];

    const int i = threadIdx.x;          // column 0..1023
    const int si = i + 1;               // padded column
    const int il = (i == 0) ? 0 : i - 1;
    const int nb = gridDim.x;
    const int bid = blockIdx.x;
    const int lane = i & 31, wid = i >> 5;
    const unsigned FULL = 0xFFFFFFFFu;
    const bool iIn = (i > 0) && (i < NX - 1);

    int base = NY / nb, rem = NY % nb;
    int r0 = bid * base + (bid < rem ? bid : rem);
    int r1 = r0 + base + (bid < rem ? 1 : 0);
    const int band = r1 - r0;           // <= 7

    const float tma = tma_p[0], tmj = tmj_p[0];
    const float CFACT = (float)(1e-17 * 8927.1 * 8927.1 * 8927.1);

    // ---- one-time init ----
    if (i < 3) {
        sZ [i * NXP] = 0.f; sZ [i * NXP + NXP - 1] = 0.f;
        sHw[i * NXP] = 0.f; sHw[i * NXP + NXP - 1] = 0.f;
        sZn[i * NXP] = 0.f; sZn[i * NXP + NXP - 1] = 0.f;
    }
    #pragma unroll
    for (int k = 0; k < 8; k++) sDb[k * NX + i] = 1e-10f;
    for (int j = r0; j < r1; j++) {
        int idx = j * NX + i;
        g_H0[idx] = 0.0f;
        g_smb[idx] = smb_of(Ztopo[idx], precip[idx], mask[idx], tma, tmj);
    }
    unsigned target = nb;
    __syncthreads();
    if (i == 0) { red_add_rel(&g_arrive, 1u); while (ld_acq(&g_arrive) < target) __nanosleep(20); }
    __syncthreads();
    target += nb;

    float time = 0.0f, tlast = 0.0f;

    for (int s = 0; s < NSTEPS; s++) {
        const float* Hr = (s & 1) ? g_H1 : g_H0;
        float*       Hw = (s & 1) ? g_H0 : g_H1;

        float maxD = (s == 0) ? 1e-10f : __int_as_float(__ldcg(&g_maxDbits[s]));
        float dt = fminf(2500.0f / (2.7f * maxD), 0.5f);
        if (!(time < 32.0f)) dt = 0.0f;
        float tnew = time + dt;
        bool  upd  = (tnew - tlast) >= 5.0f;
        const bool last = (s == NSTEPS - 1);

        // ---- prologue: stage z row r0, load zU / D row r0-1 regs ----
        int idx = r0 * NX + i;
        float zU = 0.f;
        if (r0 > 0) zU = Ztopo[idx - NX] + __ldcg(&Hr[idx - NX]);
        float hC  = Hr[idx];
        float ZtC = Ztopo[idx];
        float zC  = ZtC + hC;
        sZ[(r0 % 3) * NXP + si] = zC;
        float Dmm = sDb[il], Dm0 = sDb[i];       // slot 0 = D row r0-1
        float hw_prev = 0.f, zn_prev = 0.f;
        float lmax = 0.f;
        __syncthreads();

        // ---- fused sweep: H row j, then D(next) row j-1 ----
        for (int j = r0; j < r1; j++, idx += NX) {
            const int c = j % 3, n = (j + 1) % 3, p = (j + 2) % 3;
            const int slot = j - r0 + 1;

            // phase 1: H update of row j
            const float* hp = &Hr[idx + NX];
            float h_next  = 0.f, zt_next = 0.f;
            if (j + 1 < NY) {
                h_next  = (j + 1 < r1) ? *hp : __ldcg(hp);
                zt_next = Ztopo[idx + NX];
            }
            float z_next = zt_next + h_next;
            float zL = sZ[c * NXP + si - 1];
            float zR = sZ[c * NXP + si + 1];
            float D00 = sDb[slot * NX + i];
            float D0m = sDb[slot * NX + il];
            float smbv = g_smb[idx];

            float Hn = hC;
            if (iIn && (j > 0) && (j < NY - 1)) {
                float qxr = -(0.5f * (Dm0 + D00)) * (zR - zC) * INV;
                float qxl = -(0.5f * (Dmm + D0m)) * (zC - zL) * INV;
                float qyd = -(0.5f * (D0m + D00)) * (z_next - zC) * INV;
                float qyu = -(0.5f * (Dmm + Dm0)) * (zC - zU) * INV;
                float dHdt = -((qxr - qxl) * INV + (qyd - qyu) * INV);
                Hn = hC + dt * (dHdt + smbv);
            }
            Hn = fmaxf(Hn, 0.0f);
            Hw[idx] = Hn;
            float Zn = ZtC + Hn;

            // phase 2: stage rows
            sHw[c * NXP + si] = Hn;
            sZn[c * NXP + si] = Zn;
            sZ [n * NXP + si] = z_next;
            __syncthreads();

            // phase 3: D(next step) row j-1 (from Hn rows j-1, j)
            if (j > r0) {
                float h01 = sHw[p * NXP + si + 1], h11 = sHw[c * NXP + si + 1];
                float z01 = sZn[p * NXP + si + 1], z11 = sZn[c * NXP + si + 1];
                float H_avg = 0.25f * (((hw_prev + h11) + h01) + Hn);
                float sx = 0.5f * ((z01 - zn_prev) * INV + (z11 - Zn) * INV);
                float sy = 0.5f * ((Zn - zn_prev) * INV + (z11 - z01) * INV);
                float s2 = sx * sx + sy * sy + 1e-10f;
                float h2 = H_avg * H_avg;
                float D = CFACT * ((h2 * h2) * H_avg) * s2 + 1e-10f;
                if (i < NX - 1) {
                    sDb[(slot - 1) * NX + i] = D;
                    lmax = fmaxf(lmax, D);
                }
            }
            // rolls
            zU = zC; zC = z_next; hC = h_next; ZtC = zt_next;
            Dmm = D0m; Dm0 = D00;
            hw_prev = Hn; zn_prev = Zn;
        }

        if (last) {
            for (int j = r0; j < r1; j++) {
                int k = j * NX + i;
                out[k] = Hw[k];
            }
            break;
        }

        // ---- publish own band, overlap smb refresh with neighbor skew ----
        __syncthreads();
        if (i == 0) red_add_rel(&g_done[bid * 8], 1u);

        if (upd) {
            for (int j = r0; j < r1; j++) {
                int k = j * NX + i;
                float Hn = Hw[k];
                float Zn = Ztopo[k] + Hn;
                g_smb[k] = smb_of(Zn, precip[k], mask[k], tma, tmj);
            }
        }

        if (i == 0 && bid > 0)       { while (ld_acq(&g_done[(bid - 1) * 8]) < (unsigned)(s + 1)) __nanosleep(20); }
        if (i == 32 && bid < nb - 1) { while (ld_acq(&g_done[(bid + 1) * 8]) < (unsigned)(s + 1)) __nanosleep(20); }
        __syncthreads();

        // ---- boundary D rows via global loads ----
        if (r0 >= 1 && i < NX - 1) {            // D row r0-1 (needs neighbor row r0-1)
            int ia = (r0 - 1) * NX + i, ib = r0 * NX + i;
            float hA = __ldcg(&Hw[ia]), hAr = __ldcg(&Hw[ia + 1]);
            float hB = Hw[ib],          hBr = Hw[ib + 1];
            float z00 = Ztopo[ia] + hA, z01 = Ztopo[ia + 1] + hAr;
            float z10 = Ztopo[ib] + hB, z11 = Ztopo[ib + 1] + hBr;
            float H_avg = 0.25f * (((hA + hBr) + hAr) + hB);
            float sx = 0.5f * ((z01 - z00) * INV + (z11 - z10) * INV);
            float sy = 0.5f * ((z10 - z00) * INV + (z11 - z01) * INV);
            float s2 = sx * sx + sy * sy + 1e-10f;
            float h2 = H_avg * H_avg;
            float D = CFACT * ((h2 * h2) * H_avg) * s2 + 1e-10f;
            sDb[i] = D;
            lmax = fmaxf(lmax, D);
        }
        if (r1 <= NY - 1 && i < NX - 1) {       // D row r1-1 (needs neighbor row r1)
            int ia = (r1 - 1) * NX + i, ib = r1 * NX + i;
            float hA = Hw[ia],          hAr = Hw[ia + 1];
            float hB = __ldcg(&Hw[ib]), hBr = __ldcg(&Hw[ib + 1]);
            float z00 = Ztopo[ia] + hA, z01 = Ztopo[ia + 1] + hAr;
            float z10 = Ztopo[ib] + hB, z11 = Ztopo[ib + 1] + hBr;
            float H_avg = 0.25f * (((hA + hBr) + hAr) + hB);
            float sx = 0.5f * ((z01 - z00) * INV + (z11 - z10) * INV);
            float sy = 0.5f * ((z10 - z00) * INV + (z11 - z01) * INV);
            float s2 = sx * sx + sy * sy + 1e-10f;
            float h2 = H_avg * H_avg;
            float D = CFACT * ((h2 * h2) * H_avg) * s2 + 1e-10f;
            sDb[band * NX + i] = D;
            lmax = fmaxf(lmax, D);
        }

        // ---- max reduce -> slot s+1, then one global barrier ----
        #pragma unroll
        for (int o = 16; o > 0; o >>= 1)
            lmax = fmaxf(lmax, __shfl_xor_sync(FULL, lmax, o));
        if (lane == 0) wred[wid] = lmax;
        __syncthreads();
        if (wid == 0) {
            float m = wred[lane];
            #pragma unroll
            for (int o = 16; o > 0; o >>= 1)
                m = fmaxf(m, __shfl_xor_sync(FULL, m, o));
            if (lane == 0) atomicMax(&g_maxDbits[s + 1], __float_as_int(m));
        }
        __syncthreads();
        if (i == 0) { red_add_rel(&g_arrive, 1u); while (ld_acq(&g_arrive) < target) __nanosleep(20); }
        __syncthreads();
        target += nb;

        time = tnew;
        if (upd) tlast = tnew;
    }
}

extern "C" void kernel_launch(void* const* d_in, const int* in_sizes, int n_in,
                              void* d_out, int out_size) {
    const float* precip = (const float*)d_in[0];
    const float* tma_p  = (const float*)d_in[1];
    const float* tmj_p  = (const float*)d_in[2];
    const float* Ztopo  = (const float*)d_in[3];
    const float* mask   = (const float*)d_in[4];
    float* out = (float*)d_out;

    int dev = 0;
    cudaGetDevice(&dev);
    int sms = 0;
    cudaDeviceGetAttribute(&sms, cudaDevAttrMultiProcessorCount, dev);
    if (sms < 1) sms = 1;
    if (sms > 256) sms = 256;

    const int smem_bytes = (9 * NXP + 8 * NX) * (int)sizeof(float);
    cudaFuncSetAttribute(k_persist, cudaFuncAttributeMaxDynamicSharedMemorySize, smem_bytes);

    k_reset<<<1, 1024>>>();
    k_persist<<<sms, 1024, smem_bytes>>>(precip, tma_p, tmj_p, Ztopo, mask, out);
}